// round 16
// baseline (speedup 1.0000x reference)
#include <cuda_runtime.h>
#include <cuda_bf16.h>

#define SS   8
#define HH   544
#define WW   960
#define HID  64
#define BT   256

__device__ __forceinline__ float fast_tanh(float x)
{
    float r;
    asm("tanh.approx.f32 %0, %1;" : "=f"(r) : "f"(x));
    return r;
}

__global__ __launch_bounds__(BT)
void sky_kernel(const float* __restrict__ images,
                const float* __restrict__ extr,
                const float* __restrict__ intr,
                const float* __restrict__ W1,
                const float* __restrict__ b1,
                const float* __restrict__ W2,
                const float* __restrict__ b2,
                const float* __restrict__ pcd,
                const float* __restrict__ lsc,
                const int*   __restrict__ dsp,
                float* __restrict__ out, int N, int NW, int PERM)
{
    __shared__ float sE[SS * 12];
    __shared__ float sK[SS * 9];
    __shared__ float sW1[3 * HID];
    __shared__ float sB1[HID];
    __shared__ float sW2[HID * 3];
    __shared__ float sB2[3];

    const int tid = threadIdx.x;

    float ds;
    {
        int iv = *dsp;
        ds = (iv > 0 && iv < 1000000) ? (float)iv : __int_as_float(iv);
    }

    if (tid < SS * 12) sE[tid] = extr[(tid / 12) * 16 + (tid % 12)];
    if (tid < SS * 9) {
        int ij = tid % 9, i = ij / 3, j = ij % 3;
        float d = 1.0f;
        if (i == 0 && (j == 0 || j == 2)) d = ds;
        if (i == 1 && (j == 1 || j == 2)) d = ds;
        sK[tid] = intr[tid] / d;
    }
    if (tid < 3 * HID) sW1[tid] = W1[tid];
    if (tid < HID)     sB1[tid] = b1[tid];
    if (tid < HID * 3) sW2[tid] = W2[(tid / 3) * 6 + (tid % 3)];
    if (tid < 3)       sB2[tid] = b2[tid];
    __syncthreads();

    // warp-granularity scatter (load balance across SMs)
    const int gwarp = (blockIdx.x * BT + tid) >> 5;
    if (gwarp >= NW) return;
    const long long pw = ((long long)gwarp * PERM) % NW;
    const int n = (int)(pw << 5) + (tid & 31);
    if (n >= N) return;

    const float X = pcd[3 * n + 0];
    const float Y = pcd[3 * n + 1];
    const float Z = pcd[3 * n + 2];

    float f0 = 0.f, f1 = 0.f, f2 = 0.f, cnt = 0.f;

    // ---- camera-PAIR batched gather: issue both 12-load batches before
    //      consuming either -> halves the exposed-latency segments ----
    #pragma unroll
    for (int sp = 0; sp < SS / 2; ++sp) {
        const int s0 = 2 * sp, s1 = 2 * sp + 1;

        bool mA = false, mB = false;
        float wA00 = 0.f, wA01 = 0.f, wA10 = 0.f, wA11 = 0.f;
        float wB00 = 0.f, wB01 = 0.f, wB10 = 0.f, wB11 = 0.f;
        const float* imgA = images;
        const float* imgB = images;

        {
            const float* E = sE + s0 * 12;
            const float* K = sK + s0 * 9;
            float c0 = E[0] * X + E[1]  * Y + E[2]  * Z + E[3];
            float c1 = E[4] * X + E[5]  * Y + E[6]  * Z + E[7];
            float c2 = E[8] * X + E[9]  * Y + E[10] * Z + E[11];
            float u = K[0] * c0 + K[1] * c1 + K[2] * c2;
            float v = K[3] * c0 + K[4] * c1 + K[5] * c2;
            float w = K[6] * c0 + K[7] * c1 + K[8] * c2;
            float zs = (fabsf(w) > 1e-6f) ? w : 1e-6f;
            float px = u / zs;
            float py = v / zs;
            mA = (w > 0.001f) && (px >= 0.f) && (px <= (float)(WW - 1)) &&
                 (py >= 0.f) && (py <= (float)(HH - 1));
            if (mA) {
                int x0 = (int)floorf(px); x0 = min(max(x0, 0), WW - 2);
                int y0 = (int)floorf(py); y0 = min(max(y0, 0), HH - 2);
                float wx = px - (float)x0;
                float wy = py - (float)y0;
                wA00 = (1.f - wx) * (1.f - wy);
                wA01 = wx * (1.f - wy);
                wA10 = (1.f - wx) * wy;
                wA11 = wx * wy;
                imgA = images + (size_t)s0 * 3 * HH * WW + (size_t)y0 * WW + x0;
            }
        }
        {
            const float* E = sE + s1 * 12;
            const float* K = sK + s1 * 9;
            float c0 = E[0] * X + E[1]  * Y + E[2]  * Z + E[3];
            float c1 = E[4] * X + E[5]  * Y + E[6]  * Z + E[7];
            float c2 = E[8] * X + E[9]  * Y + E[10] * Z + E[11];
            float u = K[0] * c0 + K[1] * c1 + K[2] * c2;
            float v = K[3] * c0 + K[4] * c1 + K[5] * c2;
            float w = K[6] * c0 + K[7] * c1 + K[8] * c2;
            float zs = (fabsf(w) > 1e-6f) ? w : 1e-6f;
            float px = u / zs;
            float py = v / zs;
            mB = (w > 0.001f) && (px >= 0.f) && (px <= (float)(WW - 1)) &&
                 (py >= 0.f) && (py <= (float)(HH - 1));
            if (mB) {
                int x0 = (int)floorf(px); x0 = min(max(x0, 0), WW - 2);
                int y0 = (int)floorf(py); y0 = min(max(y0, 0), HH - 2);
                float wx = px - (float)x0;
                float wy = py - (float)y0;
                wB00 = (1.f - wx) * (1.f - wy);
                wB01 = wx * (1.f - wy);
                wB10 = (1.f - wx) * wy;
                wB11 = wx * wy;
                imgB = images + (size_t)s1 * 3 * HH * WW + (size_t)y0 * WW + x0;
            }
        }

        // --- issue both load batches (predicated), no consumption yet ---
        float A0 = 0.f, A1 = 0.f, A2 = 0.f, A3 = 0.f, A4 = 0.f, A5 = 0.f;
        float A6 = 0.f, A7 = 0.f, A8 = 0.f, A9 = 0.f, A10 = 0.f, A11 = 0.f;
        float B0 = 0.f, B1 = 0.f, B2 = 0.f, B3 = 0.f, B4 = 0.f, B5 = 0.f;
        float B6 = 0.f, B7 = 0.f, B8 = 0.f, B9 = 0.f, B10 = 0.f, B11 = 0.f;

        if (mA) {
            const float* pA = imgA;
            const float* pB = imgA + (size_t)HH * WW;
            const float* pC = imgA + (size_t)2 * HH * WW;
            A0 = __ldg(pA);      A1 = __ldg(pA + 1);
            A2 = __ldg(pA + WW); A3 = __ldg(pA + WW + 1);
            A4 = __ldg(pB);      A5 = __ldg(pB + 1);
            A6 = __ldg(pB + WW); A7 = __ldg(pB + WW + 1);
            A8 = __ldg(pC);      A9 = __ldg(pC + 1);
            A10 = __ldg(pC + WW); A11 = __ldg(pC + WW + 1);
        }
        if (mB) {
            const float* pA = imgB;
            const float* pB = imgB + (size_t)HH * WW;
            const float* pC = imgB + (size_t)2 * HH * WW;
            B0 = __ldg(pA);      B1 = __ldg(pA + 1);
            B2 = __ldg(pA + WW); B3 = __ldg(pA + WW + 1);
            B4 = __ldg(pB);      B5 = __ldg(pB + 1);
            B6 = __ldg(pB + WW); B7 = __ldg(pB + WW + 1);
            B8 = __ldg(pC);      B9 = __ldg(pC + 1);
            B10 = __ldg(pC + WW); B11 = __ldg(pC + WW + 1);
        }

        // --- consume: accumulate camera s0 then s1 (reference order) ---
        if (mA) {
            f0 += A0 * wA00 + A1 * wA01 + A2 * wA10 + A3 * wA11;
            f1 += A4 * wA00 + A5 * wA01 + A6 * wA10 + A7 * wA11;
            f2 += A8 * wA00 + A9 * wA01 + A10 * wA10 + A11 * wA11;
            cnt += 1.f;
        }
        if (mB) {
            f0 += B0 * wB00 + B1 * wB01 + B2 * wB10 + B3 * wB11;
            f1 += B4 * wB00 + B5 * wB01 + B6 * wB10 + B7 * wB11;
            f2 += B8 * wB00 + B9 * wB01 + B10 * wB10 + B11 * wB11;
            cnt += 1.f;
        }
    }

    float2* op = (float2*)(out + (size_t)6 * n);   // 24B offset -> 8B aligned

    if (cnt == 0.f) {
        op[0] = make_float2(0.f, 0.f);
        op[1] = make_float2(0.f, 0.f);
        op[2] = make_float2(0.f, 0.f);
        return;
    }

    const float inv = 1.f / cnt;
    f0 *= inv; f1 *= inv; f2 *= inv;

    float a0 = sB2[0], a1 = sB2[1], a2 = sB2[2];
    #pragma unroll
    for (int j = 0; j < HID; ++j) {
        float h = f0 * sW1[j] + f1 * sW1[HID + j] + f2 * sW1[2 * HID + j] + sB1[j];
        h = fmaxf(h, 0.f);
        a0 = fmaf(h, sW2[j * 3 + 0], a0);
        a1 = fmaf(h, sW2[j * 3 + 1], a1);
        a2 = fmaf(h, sW2[j * 3 + 2], a2);
    }

    op[0] = make_float2(fast_tanh(a0), fast_tanh(a1));
    op[1] = make_float2(fast_tanh(a2), __expf(lsc[3 * n + 0]));
    op[2] = make_float2(__expf(lsc[3 * n + 1]), __expf(lsc[3 * n + 2]));
}

extern "C" void kernel_launch(void* const* d_in, const int* in_sizes, int n_in,
                              void* d_out, int out_size)
{
    const float* images = (const float*)d_in[0];
    const float* extr   = (const float*)d_in[1];
    const float* intr   = (const float*)d_in[2];
    const float* W1     = (const float*)d_in[3];
    const float* b1     = (const float*)d_in[4];
    const float* W2     = (const float*)d_in[5];
    const float* b2     = (const float*)d_in[6];
    const float* pcd    = (const float*)d_in[7];
    const float* lsc    = (const float*)d_in[8];
    const int*   dsp    = (const int*)  d_in[9];

    int N  = in_sizes[7] / 3;
    int NW = (N + 31) / 32;

    int PERM = (int)(0.6180339887 * NW) | 1;
    while (true) {
        int a = PERM, b = NW;
        while (b) { int t = a % b; a = b; b = t; }
        if (a == 1) break;
        PERM += 2;
    }

    int blocks = (NW * 32 + BT - 1) / BT;
    sky_kernel<<<blocks, BT>>>(images, extr, intr, W1, b1, W2, b2,
                               pcd, lsc, dsp, (float*)d_out, N, NW, PERM);
}

// round 17
// speedup vs baseline: 1.0890x; 1.0890x over previous
#include <cuda_runtime.h>
#include <cuda_bf16.h>

#define SS   8
#define HH   544
#define WW   960
#define HID  64
#define BT   256

__device__ __forceinline__ float fast_tanh(float x)
{
    float r;
    asm("tanh.approx.f32 %0, %1;" : "=f"(r) : "f"(x));
    return r;
}

__global__ __launch_bounds__(BT)
void sky_kernel(const float* __restrict__ images,
                const float* __restrict__ extr,
                const float* __restrict__ intr,
                const float* __restrict__ W1,
                const float* __restrict__ b1,
                const float* __restrict__ W2,
                const float* __restrict__ b2,
                const float* __restrict__ pcd,
                const float* __restrict__ lsc,
                const int*   __restrict__ dsp,
                float* __restrict__ out, int N, int NW, int PERM)
{
    __shared__ float sE[SS * 12];
    __shared__ float sK[SS * 9];
    __shared__ float sW1[3 * HID];
    __shared__ float sB1[HID];
    __shared__ float sW2[HID * 3];
    __shared__ float sB2[3];

    const int tid = threadIdx.x;

    float ds;
    {
        int iv = *dsp;
        ds = (iv > 0 && iv < 1000000) ? (float)iv : __int_as_float(iv);
    }

    if (tid < SS * 12) sE[tid] = extr[(tid / 12) * 16 + (tid % 12)];
    if (tid < SS * 9) {
        int ij = tid % 9, i = ij / 3, j = ij % 3;
        float d = 1.0f;
        if (i == 0 && (j == 0 || j == 2)) d = ds;
        if (i == 1 && (j == 1 || j == 2)) d = ds;
        sK[tid] = intr[tid] / d;
    }
    if (tid < 3 * HID) sW1[tid] = W1[tid];
    if (tid < HID)     sB1[tid] = b1[tid];
    if (tid < HID * 3) sW2[tid] = W2[(tid / 3) * 6 + (tid % 3)];
    if (tid < 3)       sB2[tid] = b2[tid];
    __syncthreads();

    // warp-granularity scatter (load balance across SMs)
    const int gwarp = (blockIdx.x * BT + tid) >> 5;
    if (gwarp >= NW) return;
    const long long pw = ((long long)gwarp * PERM) % NW;
    const int n = (int)(pw << 5) + (tid & 31);
    if (n >= N) return;

    const float X = pcd[3 * n + 0];
    const float Y = pcd[3 * n + 1];
    const float Z = pcd[3 * n + 2];

    float f0 = 0.f, f1 = 0.f, f2 = 0.f, cnt = 0.f;

    #pragma unroll
    for (int s = 0; s < SS; ++s) {
        const float* E = sE + s * 12;
        const float* K = sK + s * 9;
        float c0 = E[0] * X + E[1]  * Y + E[2]  * Z + E[3];
        float c1 = E[4] * X + E[5]  * Y + E[6]  * Z + E[7];
        float c2 = E[8] * X + E[9]  * Y + E[10] * Z + E[11];
        float u = K[0] * c0 + K[1] * c1 + K[2] * c2;
        float v = K[3] * c0 + K[4] * c1 + K[5] * c2;
        float w = K[6] * c0 + K[7] * c1 + K[8] * c2;
        float zs = (fabsf(w) > 1e-6f) ? w : 1e-6f;
        float px = __fdividef(u, zs);   // fast div: MUFU.RCP + mul (~2 ulp)
        float py = __fdividef(v, zs);
        bool m = (w > 0.001f) && (px >= 0.f) && (px <= (float)(WW - 1)) &&
                 (py >= 0.f) && (py <= (float)(HH - 1));
        if (m) {
            int x0 = __float2int_rd(px); x0 = min(max(x0, 0), WW - 2);
            int y0 = __float2int_rd(py); y0 = min(max(y0, 0), HH - 2);
            float wx = px - (float)x0;
            float wy = py - (float)y0;
            float w00 = (1.f - wx) * (1.f - wy);
            float w01 = wx * (1.f - wy);
            float w10 = (1.f - wx) * wy;
            float w11 = wx * wy;
            const float* img = images + (size_t)s * 3 * HH * WW + (size_t)y0 * WW + x0;
            {
                const float* p = img;
                f0 += p[0] * w00 + p[1] * w01 + p[WW] * w10 + p[WW + 1] * w11;
            }
            {
                const float* p = img + (size_t)HH * WW;
                f1 += p[0] * w00 + p[1] * w01 + p[WW] * w10 + p[WW + 1] * w11;
            }
            {
                const float* p = img + (size_t)2 * HH * WW;
                f2 += p[0] * w00 + p[1] * w01 + p[WW] * w10 + p[WW + 1] * w11;
            }
            cnt += 1.f;
        }
    }

    float2* op = (float2*)(out + (size_t)6 * n);   // 24B offset -> 8B aligned

    if (cnt == 0.f) {
        op[0] = make_float2(0.f, 0.f);
        op[1] = make_float2(0.f, 0.f);
        op[2] = make_float2(0.f, 0.f);
        return;
    }

    const float inv = 1.f / cnt;
    f0 *= inv; f1 *= inv; f2 *= inv;

    float a0 = sB2[0], a1 = sB2[1], a2 = sB2[2];
    #pragma unroll
    for (int j = 0; j < HID; ++j) {
        float h = f0 * sW1[j] + f1 * sW1[HID + j] + f2 * sW1[2 * HID + j] + sB1[j];
        h = fmaxf(h, 0.f);
        a0 = fmaf(h, sW2[j * 3 + 0], a0);
        a1 = fmaf(h, sW2[j * 3 + 1], a1);
        a2 = fmaf(h, sW2[j * 3 + 2], a2);
    }

    op[0] = make_float2(fast_tanh(a0), fast_tanh(a1));
    op[1] = make_float2(fast_tanh(a2), __expf(lsc[3 * n + 0]));
    op[2] = make_float2(__expf(lsc[3 * n + 1]), __expf(lsc[3 * n + 2]));
}

extern "C" void kernel_launch(void* const* d_in, const int* in_sizes, int n_in,
                              void* d_out, int out_size)
{
    const float* images = (const float*)d_in[0];
    const float* extr   = (const float*)d_in[1];
    const float* intr   = (const float*)d_in[2];
    const float* W1     = (const float*)d_in[3];
    const float* b1     = (const float*)d_in[4];
    const float* W2     = (const float*)d_in[5];
    const float* b2     = (const float*)d_in[6];
    const float* pcd    = (const float*)d_in[7];
    const float* lsc    = (const float*)d_in[8];
    const int*   dsp    = (const int*)  d_in[9];

    int N  = in_sizes[7] / 3;
    int NW = (N + 31) / 32;

    int PERM = (int)(0.6180339887 * NW) | 1;
    while (true) {
        int a = PERM, b = NW;
        while (b) { int t = a % b; a = b; b = t; }
        if (a == 1) break;
        PERM += 2;
    }

    int blocks = (NW * 32 + BT - 1) / BT;
    sky_kernel<<<blocks, BT>>>(images, extr, intr, W1, b1, W2, b2,
                               pcd, lsc, dsp, (float*)d_out, N, NW, PERM);
}